// round 17
// baseline (speedup 1.0000x reference)
#include <cuda_runtime.h>
#include <cuda_bf16.h>
#include <cuda_fp16.h>
#include <math.h>

#define NNODES 100000
#define FIN    512
#define HID    256
#define NC     40
#define KSTEPS 10
#define EMAX   3200000
#define ALPHA  0.1f

// ---------------- device scratch (no allocations allowed) ----------------
__device__ float g_hid[NNODES * HID];      // 102 MB fp32 hid
__device__ float g_h  [NNODES * NC];       // 16 MB (fp32 h for injection)
__device__ __half g_h16 [NNODES * NC];     // 8 MB (fp16 h for step-1 gather)
__device__ __half g_z16A[NNODES * NC];     // 8 MB ping
__device__ __half g_z16B[NNODES * NC];     // 8 MB pong
__device__ float g_dinv[NNODES];
__device__ int   g_deg [NNODES];
__device__ int   g_rowptr[NNODES + 1];
__device__ int   g_fill[NNODES];
__device__ int2  g_edge[EMAX];             // (col, ew bits) packed

// fp16 W1 (transposed) for tensor-core gemm1
__device__ __half g_wT[HID * FIN];         // [n][k], 0.26 MB

// ---------------- graph preprocessing ----------------
__global__ void zero_deg_kernel() {
    int i = blockIdx.x * blockDim.x + threadIdx.x;
    if (i < NNODES) g_deg[i] = 0;
}

__global__ void count_deg_kernel(const int* __restrict__ ei, int E) {
    int e = blockIdx.x * blockDim.x + threadIdx.x;
    if (e < E) atomicAdd(&g_deg[ei[e]], 1);
}

__global__ void scan_kernel(int E) {
    const int T = 1024;
    const int CH = (NNODES + T - 1) / T;
    int t = threadIdx.x;
    int beg = t * CH;
    int end = beg + CH; if (end > NNODES) end = NNODES;
    if (beg > NNODES) beg = NNODES;

    int sum = 0;
    for (int i = beg; i < end; i++) sum += g_deg[i];

    __shared__ int sh[1024];
    sh[t] = sum;
    __syncthreads();
    for (int off = 1; off < T; off <<= 1) {
        int v = (t >= off) ? sh[t - off] : 0;
        __syncthreads();
        sh[t] += v;
        __syncthreads();
    }
    int offset = sh[t] - sum;

    int running = offset;
    for (int i = beg; i < end; i++) {
        g_rowptr[i] = running;
        g_fill[i]   = running;
        g_dinv[i]   = rsqrtf((float)(g_deg[i] + 1));   // +1 self-loop
        running += g_deg[i];
    }
    if (t == T - 1) g_rowptr[NNODES] = sh[T - 1];
}

__global__ void scatter_kernel(const int* __restrict__ ei, int E) {
    int e = blockIdx.x * blockDim.x + threadIdx.x;
    if (e >= E) return;
    int r = ei[e];          // destination
    int c = ei[E + e];      // source
    int pos = atomicAdd(&g_fill[r], 1);
    g_edge[pos] = make_int2(c, __float_as_int(g_dinv[r] * g_dinv[c]));
}

// ---------------- W1 fp16 conversion (tiny: 0.26 MB) ----------------
__global__ void convert_w_kernel(const float* __restrict__ W1) {
    int i = blockIdx.x * blockDim.x + threadIdx.x;     // over FIN*HID
    if (i >= FIN * HID) return;
    int k = i / HID, n = i - k * HID;
    g_wT[n * FIN + k] = __float2half_rn(W1[i]);
}

// ---------------- helpers for mma path ----------------
__device__ __forceinline__ unsigned smem_u32(const void* p) {
    return (unsigned)__cvta_generic_to_shared(p);
}
__device__ __forceinline__ void cpasync16(unsigned saddr, const void* gaddr) {
    asm volatile("cp.async.cg.shared.global [%0], [%1], 16;\n" :: "r"(saddr), "l"(gaddr));
}
__device__ __forceinline__ void ldmatrix_x4(unsigned* r, unsigned addr) {
    asm volatile("ldmatrix.sync.aligned.m8n8.x4.shared.b16 {%0,%1,%2,%3}, [%4];\n"
                 : "=r"(r[0]), "=r"(r[1]), "=r"(r[2]), "=r"(r[3]) : "r"(addr));
}
__device__ __forceinline__ void mma_f16(float* d, const unsigned* a, const unsigned* b) {
    asm volatile("mma.sync.aligned.m16n8k16.row.col.f32.f16.f16.f32 "
                 "{%0,%1,%2,%3}, {%4,%5,%6,%7}, {%8,%9}, {%0,%1,%2,%3};\n"
                 : "+f"(d[0]), "+f"(d[1]), "+f"(d[2]), "+f"(d[3])
                 : "r"(a[0]), "r"(a[1]), "r"(a[2]), "r"(a[3]), "r"(b[0]), "r"(b[1]));
}
__device__ __forceinline__ unsigned pack_h16x2(__half lo, __half hi) {
    unsigned short ul = *(unsigned short*)&lo, uh = *(unsigned short*)&hi;
    return (unsigned)ul | ((unsigned)uh << 16);
}

// swizzled offset within a [rows x 32] half tile (64B rows, 4 x 16B chunks).
__device__ __forceinline__ unsigned swz32(int r, int ch) {
    return (unsigned)(r * 64 + ((ch ^ ((r >> 1) & 3)) << 4));
}

// ---------------- GEMM1: h1 = relu(x@W1+b1), fp16 MMA, 1024 threads --------------
// BM=128 BN=256 BK=32 (16 chunks); 32 warps (8/SMSP for latency hiding),
// warp tile 32x32 -> acc 32 regs/thread, ~64 regs total (full RF at 1 CTA/SM).
#define NCHUNK 16

__global__ __launch_bounds__(1024) void gemm1_kernel(
    const float* __restrict__ X, const float* __restrict__ b1)
{
    __shared__ __half sX[2][128 * 32];   // 8KB each
    __shared__ __half sW[2][256 * 32];   // 16KB each  (total 48KB)

    const int tid  = threadIdx.x;
    const int lane = tid & 31;
    const int wid  = tid >> 5;
    const int wm   = wid & 3;      // 4 warps along M (32 rows)
    const int wn   = wid >> 2;     // 8 warps along N (32 cols)
    const int m0 = blockIdx.x * 128;

    // X: row = tid>>3, quad = tid&7 -> 4 floats at quad*4
    const int ar = tid >> 3;
    const int aq = tid & 7;
    int arow = m0 + ar; if (arow > NNODES - 1) arow = NNODES - 1;
    const float* xsrc = X + (size_t)arow * FIN + aq * 4;
    const unsigned stsOff = swz32(ar, aq >> 1) + (aq & 1) * 8;

    // W: row = tid>>2, chunk = tid&3 (one 16B chunk per thread)
    const unsigned wOff = swz32(tid >> 2, tid & 3);
    const __half* wsrc = g_wT + (size_t)(tid >> 2) * FIN + (tid & 3) * 8;

    float acc[2][4][4];
    #pragma unroll
    for (int mf = 0; mf < 2; mf++)
        #pragma unroll
        for (int nf = 0; nf < 4; nf++)
            #pragma unroll
            for (int q = 0; q < 4; q++) acc[mf][nf][q] = 0.0f;

    float4 xc = *(const float4*)xsrc;
    {
        cpasync16(smem_u32(sW[0]) + wOff, wsrc);
        asm volatile("cp.async.commit_group;\n" ::);
    }

    for (int i = 0; i < NCHUNK; i++) {
        const int buf = i & 1;
        float4 xn;
        if (i + 1 < NCHUNK) {
            xn = *(const float4*)(xsrc + (i + 1) * 32);
            cpasync16(smem_u32(sW[buf ^ 1]) + wOff, wsrc + (i + 1) * 32);
            asm volatile("cp.async.commit_group;\n" ::);
            asm volatile("cp.async.wait_group 1;\n" ::);
        } else {
            asm volatile("cp.async.wait_group 0;\n" ::);
        }

        // convert 4 fp32 -> 4 fp16, one 8B STS
        {
            uint2 v;
            v.x = pack_h16x2(__float2half_rn(xc.x), __float2half_rn(xc.y));
            v.y = pack_h16x2(__float2half_rn(xc.z), __float2half_rn(xc.w));
            *(uint2*)((char*)sX[buf] + stsOff) = v;
        }
        __syncthreads();

        {
            const unsigned xb = smem_u32(sX[buf]);
            const unsigned wb = smem_u32(sW[buf]);
            #pragma unroll
            for (int ks = 0; ks < 2; ks++) {
                unsigned fx[2][4];
                #pragma unroll
                for (int mf = 0; mf < 2; mf++) {
                    int row = wm * 32 + mf * 16 + (lane & 15);
                    int ch  = ks * 2 + (lane >> 4);
                    ldmatrix_x4(fx[mf], xb + swz32(row, ch));
                }
                unsigned fb[4][2];
                #pragma unroll
                for (int np = 0; np < 2; np++) {
                    int mat = lane >> 3, rr = lane & 7;
                    int n  = wn * 32 + np * 16 + (mat >> 1) * 8 + rr;
                    int ch = ks * 2 + (mat & 1);
                    unsigned t[4];
                    ldmatrix_x4(t, wb + swz32(n, ch));
                    fb[np * 2][0] = t[0];     fb[np * 2][1] = t[1];
                    fb[np * 2 + 1][0] = t[2]; fb[np * 2 + 1][1] = t[3];
                }
                #pragma unroll
                for (int mf = 0; mf < 2; mf++)
                    #pragma unroll
                    for (int nf = 0; nf < 4; nf++)
                        mma_f16(acc[mf][nf], fx[mf], fb[nf]);
            }
        }
        __syncthreads();
        xc = xn;
    }

    // epilogue: relu(acc + bias) -> g_hid fp32
    const int g  = lane >> 2;
    const int c2 = (lane & 3) * 2;
    #pragma unroll
    for (int mf = 0; mf < 2; mf++) {
        #pragma unroll
        for (int nf = 0; nf < 4; nf++) {
            int n = wn * 32 + nf * 8 + c2;
            float bn0 = b1[n], bn1 = b1[n + 1];
            int m_lo = m0 + wm * 32 + mf * 16 + g;
            int m_hi = m_lo + 8;
            if (m_lo < NNODES) {
                float2 v = make_float2(fmaxf(acc[mf][nf][0] + bn0, 0.0f),
                                       fmaxf(acc[mf][nf][1] + bn1, 0.0f));
                *(float2*)&g_hid[(size_t)m_lo * HID + n] = v;
            }
            if (m_hi < NNODES) {
                float2 v = make_float2(fmaxf(acc[mf][nf][2] + bn0, 0.0f),
                                       fmaxf(acc[mf][nf][3] + bn1, 0.0f));
                *(float2*)&g_hid[(size_t)m_hi * HID + n] = v;
            }
        }
    }
}

// ---------------- GEMM2: h = hid @ W2 + b2, writes fp32 + fp16 copies -------------
__global__ __launch_bounds__(256) void gemm2_kernel(
    const float* __restrict__ W2, const float* __restrict__ b2)
{
    __shared__ float Hs[32][65];
    __shared__ float Ws[32][40];

    int tid = threadIdx.x;
    int m0 = blockIdx.x * 64;
    int tx = tid & 7;        // 8 -> 5 cols each
    int ty = tid >> 3;       // 32 -> 2 rows each

    float acc[2][5];
    #pragma unroll
    for (int r = 0; r < 2; r++)
        #pragma unroll
        for (int j = 0; j < 5; j++) acc[r][j] = 0.0f;

    for (int k0 = 0; k0 < HID; k0 += 32) {
        {
            int kk = tid & 31;
            int mb = tid >> 5;
            #pragma unroll
            for (int mi = 0; mi < 8; mi++) {
                int m = mi * 8 + mb;
                float v = 0.0f;
                if (m0 + m < NNODES)
                    v = g_hid[(size_t)(m0 + m) * HID + k0 + kk];
                Hs[kk][m] = v;
            }
        }
        #pragma unroll
        for (int l = 0; l < 5; l++) {
            int idx = tid + l * 256;
            int kr = idx / 40;
            int n = idx - kr * 40;
            Ws[kr][n] = W2[(size_t)(k0 + kr) * NC + n];
        }
        __syncthreads();

        #pragma unroll
        for (int k = 0; k < 32; k++) {
            float a0 = Hs[k][ty * 2];
            float a1 = Hs[k][ty * 2 + 1];
            #pragma unroll
            for (int j = 0; j < 5; j++) {
                float b = Ws[k][tx * 5 + j];
                acc[0][j] += a0 * b;
                acc[1][j] += a1 * b;
            }
        }
        __syncthreads();
    }

    #pragma unroll
    for (int r = 0; r < 2; r++) {
        int m = m0 + ty * 2 + r;
        if (m < NNODES) {
            #pragma unroll
            for (int j = 0; j < 5; j++) {
                int n = tx * 5 + j;
                float v = acc[r][j] + b2[n];
                g_h[(size_t)m * NC + n] = v;
                g_h16[(size_t)m * NC + n] = __float2half_rn(v);
            }
        }
    }
}

// ---------------- fp16 gather helper ----------------
__device__ __forceinline__ float4 ldz16(const __half* p) {
    uint2 raw = *(const uint2*)p;
    __half2 a = *(__half2*)&raw.x;
    __half2 b = *(__half2*)&raw.y;
    float2 fa = __half22float2(a), fb = __half22float2(b);
    return make_float4(fa.x, fa.y, fb.x, fb.y);
}

#define SPMM_BLOCKS 1216   // 152 SM x 8 CTAs: persistent-strided

// ---------------- APPNP step (fp16 z): zout = 0.9*A_norm*zin + 0.1*h --------------
__global__ __launch_bounds__(256) void spmm16_kernel(int srcSel, int dstSel) {
    const __half* zin  = (srcSel == 0) ? g_h16 : (srcSel == 1 ? g_z16A : g_z16B);
    __half*       zout = (dstSel == 1) ? g_z16A : g_z16B;

    const int lane = threadIdx.x & 31;
    const int gw = (blockIdx.x * blockDim.x + threadIdx.x) >> 5;
    const int NW = (SPMM_BLOCKS * 256) >> 5;

    const int sub = lane / 10;
    const int cg  = lane - sub * 10;

    for (int w = gw; w < NNODES; w += NW) {
        int s = g_rowptr[w];
        int e = g_rowptr[w + 1];

        float4 acc = make_float4(0.f, 0.f, 0.f, 0.f);
        if (sub < 3) {
            #pragma unroll 4
            for (int j = s + sub; j < e; j += 3) {
                int2 ed = __ldg(&g_edge[j]);
                float wt = __int_as_float(ed.y);
                float4 zv = ldz16(zin + (size_t)ed.x * NC + cg * 4);
                acc.x += wt * zv.x;
                acc.y += wt * zv.y;
                acc.z += wt * zv.z;
                acc.w += wt * zv.w;
            }
        }

        float tx1 = __shfl_down_sync(0xffffffff, acc.x, 10);
        float ty1 = __shfl_down_sync(0xffffffff, acc.y, 10);
        float tz1 = __shfl_down_sync(0xffffffff, acc.z, 10);
        float tw1 = __shfl_down_sync(0xffffffff, acc.w, 10);
        float tx2 = __shfl_down_sync(0xffffffff, acc.x, 20);
        float ty2 = __shfl_down_sync(0xffffffff, acc.y, 20);
        float tz2 = __shfl_down_sync(0xffffffff, acc.z, 20);
        float tw2 = __shfl_down_sync(0xffffffff, acc.w, 20);

        if (lane < 10) {
            acc.x += tx1 + tx2;
            acc.y += ty1 + ty2;
            acc.z += tz1 + tz2;
            acc.w += tw1 + tw2;

            float dv = g_dinv[w];
            float ws = dv * dv;
            float4 zr = ldz16(zin + (size_t)w * NC + cg * 4);
            acc.x += ws * zr.x;
            acc.y += ws * zr.y;
            acc.z += ws * zr.z;
            acc.w += ws * zr.w;

            float4 hr = *(const float4*)(g_h + (size_t)w * NC + cg * 4);
            float ox = (1.0f - ALPHA) * acc.x + ALPHA * hr.x;
            float oy = (1.0f - ALPHA) * acc.y + ALPHA * hr.y;
            float oz = (1.0f - ALPHA) * acc.z + ALPHA * hr.z;
            float ow = (1.0f - ALPHA) * acc.w + ALPHA * hr.w;
            __half2 q0 = __floats2half2_rn(ox, oy);
            __half2 q1 = __floats2half2_rn(oz, ow);
            uint2 packed = make_uint2(*(unsigned*)&q0, *(unsigned*)&q1);
            *(uint2*)(zout + (size_t)w * NC + cg * 4) = packed;
        }
    }
}

// ---------------- final APPNP step fused with log_softmax -> out fp32 --------------
__global__ __launch_bounds__(256) void spmm_last_kernel(float* __restrict__ out) {
    const __half* zin = g_z16A;    // step 9 output

    const int lane = threadIdx.x & 31;
    const int gw = (blockIdx.x * blockDim.x + threadIdx.x) >> 5;
    const int NW = (SPMM_BLOCKS * 256) >> 5;

    const int sub = lane / 10;
    const int cg  = lane - sub * 10;

    for (int w = gw; w < NNODES; w += NW) {
        int s = g_rowptr[w];
        int e = g_rowptr[w + 1];

        float4 acc = make_float4(0.f, 0.f, 0.f, 0.f);
        if (sub < 3) {
            #pragma unroll 4
            for (int j = s + sub; j < e; j += 3) {
                int2 ed = __ldg(&g_edge[j]);
                float wt = __int_as_float(ed.y);
                float4 zv = ldz16(zin + (size_t)ed.x * NC + cg * 4);
                acc.x += wt * zv.x;
                acc.y += wt * zv.y;
                acc.z += wt * zv.z;
                acc.w += wt * zv.w;
            }
        }

        float tx1 = __shfl_down_sync(0xffffffff, acc.x, 10);
        float ty1 = __shfl_down_sync(0xffffffff, acc.y, 10);
        float tz1 = __shfl_down_sync(0xffffffff, acc.z, 10);
        float tw1 = __shfl_down_sync(0xffffffff, acc.w, 10);
        float tx2 = __shfl_down_sync(0xffffffff, acc.x, 20);
        float ty2 = __shfl_down_sync(0xffffffff, acc.y, 20);
        float tz2 = __shfl_down_sync(0xffffffff, acc.z, 20);
        float tw2 = __shfl_down_sync(0xffffffff, acc.w, 20);

        float ox = 0.f, oy = 0.f, oz = 0.f, ow = 0.f;
        float mloc = -3.4e38f;
        if (lane < 10) {
            acc.x += tx1 + tx2;
            acc.y += ty1 + ty2;
            acc.z += tz1 + tz2;
            acc.w += tw1 + tw2;

            float dv = g_dinv[w];
            float ws = dv * dv;
            float4 zr = ldz16(zin + (size_t)w * NC + cg * 4);
            acc.x += ws * zr.x;
            acc.y += ws * zr.y;
            acc.z += ws * zr.z;
            acc.w += ws * zr.w;

            float4 hr = *(const float4*)(g_h + (size_t)w * NC + cg * 4);
            ox = (1.0f - ALPHA) * acc.x + ALPHA * hr.x;
            oy = (1.0f - ALPHA) * acc.y + ALPHA * hr.y;
            oz = (1.0f - ALPHA) * acc.z + ALPHA * hr.z;
            ow = (1.0f - ALPHA) * acc.w + ALPHA * hr.w;
            mloc = fmaxf(fmaxf(ox, oy), fmaxf(oz, ow));
        }

        #pragma unroll
        for (int off = 8; off > 0; off >>= 1)
            mloc = fmaxf(mloc, __shfl_xor_sync(0xffffffff, mloc, off, 16));

        float sloc = 0.0f;
        if (lane < 10)
            sloc = __expf(ox - mloc) + __expf(oy - mloc) + __expf(oz - mloc) + __expf(ow - mloc);
        #pragma unroll
        for (int off = 8; off > 0; off >>= 1)
            sloc += __shfl_xor_sync(0xffffffff, sloc, off, 16);

        if (lane < 10) {
            float lse = mloc + logf(sloc);
            float4 o = make_float4(ox - lse, oy - lse, oz - lse, ow - lse);
            *(float4*)(out + (size_t)w * NC + cg * 4) = o;
        }
    }
}

// ---------------- launch ----------------
extern "C" void kernel_launch(void* const* d_in, const int* in_sizes, int n_in,
                              void* d_out, int out_size) {
    const float* x  = (const float*)d_in[0];
    const float* W1 = (const float*)d_in[1];
    const float* b1 = (const float*)d_in[2];
    const float* W2 = (const float*)d_in[3];
    const float* b2 = (const float*)d_in[4];
    const int*   ei = (const int*)d_in[5];
    float* out = (float*)d_out;
    int E = in_sizes[5] / 2;

    // side stream for graph preprocessing (independent of MLP until spmm)
    static cudaStream_t s2 = nullptr;
    static cudaEvent_t evFork = nullptr, evJoin = nullptr;
    if (s2 == nullptr) {
        cudaStreamCreateWithFlags(&s2, cudaStreamNonBlocking);
        cudaEventCreateWithFlags(&evFork, cudaEventDisableTiming);
        cudaEventCreateWithFlags(&evJoin, cudaEventDisableTiming);
    }

    cudaEventRecord(evFork, 0);
    cudaStreamWaitEvent(s2, evFork, 0);

    // --- side stream: graph preprocessing -> CSR + normalized weights ---
    zero_deg_kernel<<<(NNODES + 255) / 256, 256, 0, s2>>>();
    count_deg_kernel<<<(E + 255) / 256, 256, 0, s2>>>(ei, E);
    scan_kernel<<<1, 1024, 0, s2>>>(E);
    scatter_kernel<<<(E + 255) / 256, 256, 0, s2>>>(ei, E);
    cudaEventRecord(evJoin, s2);

    // --- main stream: MLP encoder ---
    convert_w_kernel<<<(FIN * HID + 255) / 256, 256>>>(W1);
    gemm1_kernel<<<(NNODES + 127) / 128, 1024>>>(x, b1);
    gemm2_kernel<<<(NNODES + 63) / 64, 256>>>(W2, b2);

    // join: spmm needs both g_h/g_h16 (main) and CSR (s2)
    cudaStreamWaitEvent(0, evJoin, 0);

    // steps 1..9 on fp16 z (persistent-strided); step 10 fused with log_softmax
    for (int i = 1; i <= KSTEPS - 1; i++) {
        int src = (i == 1) ? 0 : ((i & 1) ? 2 : 1);
        int dst = (i & 1) ? 1 : 2;
        spmm16_kernel<<<SPMM_BLOCKS, 256>>>(src, dst);
    }
    spmm_last_kernel<<<SPMM_BLOCKS, 256>>>(out);   // reads g_z16A (step-9 output)
}